// round 15
// baseline (speedup 1.0000x reference)
#include <cuda_runtime.h>
#include <cuda_fp16.h>
#include <math.h>
#include <stdint.h>

// Problem constants
#define RES    8192
#define TSTEPS 1024
#define SDIM   128

// Main kernel config
#define NBLK    128     // persistent blocks, 1 per SM
#define RPB     64      // rows of W_res per block
#define THREADS 512     // 16 warps, 4 rows per warp (128 regs/thread budget)
#define RPW     4       // rows per warp
#define CPIN    1536    // cols pinned in SMEM  (64*1536*2B = 192 KB/SM, 24 MiB chip)
#define CREG    1024    // cols pinned in REGISTERS (64 regs/lane, 16 MiB chip)
#define CSTR    (CPIN + CREG)          // 2560: streamed cols start
#define NSTRIT  ((RES - CSTR) / 128)   // 44 streamed 128-col tiles (88 MiB chip)

// Scratch (static device globals -- no allocations allowed)
__device__ __half  g_Wh[(size_t)RES * RES];            // 128 MiB fp16 weights
__device__ float   g_inproj[(size_t)TSTEPS * RES];     // 32 MiB
__device__ float   g_rbuf[2][RES];                     // double-buffered state
__device__ unsigned g_count;                           // barrier arrivals
__device__ unsigned g_gen;                             // barrier generation

// ---- packed f32x2 FMA (Blackwell dual-FMA; ptxas never emits it from C++) --
#define FFMA2(ACC, A, B) \
    asm("fma.rn.f32x2 %0, %1, %2, %0;" : "+l"(ACC) : "l"(A), "l"(B))
#define PACKF2(D, F2) \
    asm("mov.b64 %0, {%1, %2};" : "=l"(D) : "f"((F2).x), "f"((F2).y))
#define UNPACKF2(LO, HI, S) \
    asm("mov.b64 {%0, %1}, %2;" : "=f"(LO), "=f"(HI) : "l"(S))

// Process 4 cols (uint2 = 2 half2) of one row against packed r pairs RVL/RVH.
#define ACC4(Q, RVL, RVH, ACC)                                                \
{                                                                             \
    float2 _u0 = __half22float2(*(__half2*)&(Q).x);                           \
    float2 _u1 = __half22float2(*(__half2*)&(Q).y);                           \
    uint64_t _p0, _p1;                                                        \
    PACKF2(_p0, _u0); PACKF2(_p1, _u1);                                       \
    FFMA2((ACC), _p0, (RVL));                                                 \
    FFMA2((ACC), _p1, (RVH));                                                 \
}

// ---------------------------------------------------------------------------
// fp32 -> fp16 weight conversion
// ---------------------------------------------------------------------------
__global__ void convert_kernel(const float* __restrict__ W) {
    size_t i = ((size_t)blockIdx.x * blockDim.x + threadIdx.x) * 4;
    float4 v = *(const float4*)(W + i);
    __half2* o = (__half2*)(g_Wh + i);
    o[0] = __floats2half2_rn(v.x, v.y);
    o[1] = __floats2half2_rn(v.z, v.w);
}

// ---------------------------------------------------------------------------
// in_proj[t][j] = b[j] + sum_k in_seq[t][k] * W_in[j][k]
// ---------------------------------------------------------------------------
__global__ void inproj_kernel(const float* __restrict__ in_seq,
                              const float* __restrict__ W_in,
                              const float* __restrict__ b_res) {
    extern __shared__ float sm[];
    float* Ws = sm;                 // [128][129] padded
    float* Us = sm + 128 * 129;     // [64][128]
    const int jb  = blockIdx.x * 128;
    const int tb  = blockIdx.y * 64;
    const int tid = threadIdx.x;

    for (int idx = tid; idx < 128 * 128; idx += 128) {
        int r = idx >> 7, k = idx & 127;
        Ws[r * 129 + k] = W_in[(size_t)(jb + r) * SDIM + k];
    }
    for (int idx = tid; idx < 64 * 128; idx += 128) {
        int t = idx >> 7, k = idx & 127;
        Us[idx] = in_seq[(size_t)(tb + t) * SDIM + k];
    }
    __syncthreads();

    const int j = jb + tid;
    const float bj = b_res[j];
    for (int tg = 0; tg < 64; tg += 4) {
        float a0 = bj, a1 = bj, a2 = bj, a3 = bj;
        #pragma unroll 4
        for (int k = 0; k < 128; k++) {
            float w = Ws[tid * 129 + k];
            a0 = fmaf(w, Us[(tg + 0) * 128 + k], a0);
            a1 = fmaf(w, Us[(tg + 1) * 128 + k], a1);
            a2 = fmaf(w, Us[(tg + 2) * 128 + k], a2);
            a3 = fmaf(w, Us[(tg + 3) * 128 + k], a3);
        }
        g_inproj[(size_t)(tb + tg + 0) * RES + j] = a0;
        g_inproj[(size_t)(tb + tg + 1) * RES + j] = a1;
        g_inproj[(size_t)(tb + tg + 2) * RES + j] = a2;
        g_inproj[(size_t)(tb + tg + 3) * RES + j] = a3;
    }
}

// ---------------------------------------------------------------------------
// Persistent recurrent kernel. Per-block slice = 64 rows x 8192 cols fp16:
//   cols [0,1536)     SMEM-pinned  (192 KB/SM, 24 MiB chip)
//   cols [1536,2560)  REGISTER-pinned (64 regs/lane, 16 MiB chip)
//   cols [2560,8192)  streamed, zigzag order across timesteps (88 MiB chip,
//                     L2-resident under LRU with alternating sweep)
// Issue schedule: 11 straight-line microgroups of (4 streamed tiles, 1 pinned
// tile, 1 register iter) + tail (1 pinned, 5 register) -- FMA bursts stay
// short so the LTS stream never idles. MACs use packed fma.rn.f32x2 (dual
// FMA) to halve fma-pipe issue count. No conditionals in the body.
// ---------------------------------------------------------------------------
__global__ void __launch_bounds__(THREADS, 1)
esn_kernel(const float* __restrict__ res_state, float* __restrict__ out) {
    extern __shared__ char smraw[];
    float*  r_s  = (float*)smraw;                       // 32 KB state copy
    __half* wpin = (__half*)(smraw + RES * sizeof(float));  // 192 KB pinned W

    const int tid   = threadIdx.x;
    const int rbase = blockIdx.x * RPB;
    const int w     = tid >> 5;
    const int lane  = tid & 31;
    const int lr0   = RPW * w;                     // this warp's first local row
    const int r0g   = rbase + lr0;                 // global first row (mult of 4)

    // Pin SMEM region: cols [0, CPIN) of this block's 64 rows
    for (int idx = tid; idx < RPB * CPIN / 8; idx += THREADS) {
        int r = idx / (CPIN / 8);
        int c = idx % (CPIN / 8);
        *(uint4*)(wpin + r * CPIN + c * 8) =
            *(const uint4*)(g_Wh + (size_t)(rbase + r) * RES + c * 8);
    }

    // Pin REGISTER region: cols [CPIN, CSTR). Lane owns col pair
    // CPIN + 64k + 2*lane, k=0..15, for its 4 rows. 64 uint regs.
    uint32_t wreg[RPW][16];
    #pragma unroll
    for (int j = 0; j < RPW; j++) {
        const __half* src = g_Wh + (size_t)(rbase + lr0 + j) * RES + CPIN + 2 * lane;
        #pragma unroll
        for (int k = 0; k < 16; k++)
            wreg[j][k] = *(const uint32_t*)(src + 64 * k);
    }

    unsigned gen = 0;
    if (tid == 0) gen = *((volatile unsigned*)&g_gen);

    const __half* gw0 = g_Wh + (size_t)(rbase + lr0) * RES;  // row lr0 base
    const __half* sp0 = wpin + lr0 * CPIN;

    for (int t = 0; t < TSTEPS; t++) {
        // Load current state into SMEM. Cross-SM producer -> must bypass L1.
        const float* rsrc = (t == 0) ? res_state : g_rbuf[(t + 1) & 1];
        for (int i = tid; i < RES / 4; i += THREADS)
            ((float4*)r_s)[i] = __ldcg((const float4*)rsrc + i);
        __syncthreads();

        uint64_t acc0 = 0, acc1 = 0, acc2 = 0, acc3 = 0;

        #define STREAM_TILE(IT)                                               \
        {                                                                     \
            int c = CSTR + (IT) * 128 + 4 * lane;                             \
            const __half* gp = gw0 + c;                                       \
            uint2 q0 = *(const uint2*)(gp);                                   \
            uint2 q1 = *(const uint2*)(gp + RES);                             \
            uint2 q2 = *(const uint2*)(gp + 2 * RES);                         \
            uint2 q3 = *(const uint2*)(gp + 3 * RES);                         \
            ulonglong2 rv = *(const ulonglong2*)(r_s + c);                    \
            ACC4(q0, rv.x, rv.y, acc0); ACC4(q1, rv.x, rv.y, acc1);           \
            ACC4(q2, rv.x, rv.y, acc2); ACC4(q3, rv.x, rv.y, acc3);           \
        }
        #define PIN_TILE(IT)                                                  \
        {                                                                     \
            int c = (IT) * 128 + 4 * lane;                                    \
            const __half* sq = sp0 + c;                                       \
            uint2 q0 = *(const uint2*)(sq);                                   \
            uint2 q1 = *(const uint2*)(sq + CPIN);                            \
            uint2 q2 = *(const uint2*)(sq + 2 * CPIN);                        \
            uint2 q3 = *(const uint2*)(sq + 3 * CPIN);                        \
            ulonglong2 rv = *(const ulonglong2*)(r_s + c);                    \
            ACC4(q0, rv.x, rv.y, acc0); ACC4(q1, rv.x, rv.y, acc1);           \
            ACC4(q2, rv.x, rv.y, acc2); ACC4(q3, rv.x, rv.y, acc3);           \
        }
        #define REG_IT(K)                                                     \
        {                                                                     \
            uint64_t rr = *(const uint64_t*)(r_s + CPIN + 64 * (K) + 2 * lane); \
            float2 _u; uint64_t _p;                                           \
            _u = __half22float2(*(__half2*)&wreg[0][(K)]);                    \
            PACKF2(_p, _u); FFMA2(acc0, _p, rr);                              \
            _u = __half22float2(*(__half2*)&wreg[1][(K)]);                    \
            PACKF2(_p, _u); FFMA2(acc1, _p, rr);                              \
            _u = __half22float2(*(__half2*)&wreg[2][(K)]);                    \
            PACKF2(_p, _u); FFMA2(acc2, _p, rr);                              \
            _u = __half22float2(*(__half2*)&wreg[3][(K)]);                    \
            PACKF2(_p, _u); FFMA2(acc3, _p, rr);                              \
        }

        // 11 microgroups (4 streamed + 1 pinned + 1 reg) + tail (1 pin, 5 reg)
        if ((t & 1) == 0) {
            #pragma unroll
            for (int g = 0; g < 11; g++) {
                STREAM_TILE(4 * g + 0); STREAM_TILE(4 * g + 1);
                STREAM_TILE(4 * g + 2); STREAM_TILE(4 * g + 3);
                PIN_TILE(g);
                REG_IT(g);
            }
        } else {
            #pragma unroll
            for (int g = 0; g < 11; g++) {
                STREAM_TILE(43 - 4 * g); STREAM_TILE(42 - 4 * g);
                STREAM_TILE(41 - 4 * g); STREAM_TILE(40 - 4 * g);
                PIN_TILE(g);
                REG_IT(g);
            }
        }
        PIN_TILE(11);
        REG_IT(11); REG_IT(12); REG_IT(13); REG_IT(14); REG_IT(15);

        #undef STREAM_TILE
        #undef PIN_TILE
        #undef REG_IT

        float lo, hi, s0, s1, s2, s3;
        UNPACKF2(lo, hi, acc0); s0 = lo + hi;
        UNPACKF2(lo, hi, acc1); s1 = lo + hi;
        UNPACKF2(lo, hi, acc2); s2 = lo + hi;
        UNPACKF2(lo, hi, acc3); s3 = lo + hi;
        #pragma unroll
        for (int off = 16; off; off >>= 1) {
            s0 += __shfl_xor_sync(0xffffffffu, s0, off);
            s1 += __shfl_xor_sync(0xffffffffu, s1, off);
            s2 += __shfl_xor_sync(0xffffffffu, s2, off);
            s3 += __shfl_xor_sync(0xffffffffu, s3, off);
        }

        if (lane == 0) {
            float4 ipv = *(const float4*)(g_inproj + (size_t)t * RES + r0g);
            float4 y;
            y.x = tanhf(s0 + ipv.x);
            y.y = tanhf(s1 + ipv.y);
            y.z = tanhf(s2 + ipv.z);
            y.w = tanhf(s3 + ipv.w);
            *(float4*)(g_rbuf[t & 1] + r0g) = y;       // state for next step
            *(float4*)(out + (size_t)t * RES + r0g) = y;
            __threadfence();   // release this warp's state writes
        }

        // ---- grid-wide barrier (sense via generation counter) ----
        __syncthreads();
        if (tid == 0) {
            gen++;
            unsigned prev = atomicAdd(&g_count, 1u);
            if (prev == NBLK - 1) {
                atomicExch(&g_count, 0u);
                __threadfence();
                *((volatile unsigned*)&g_gen) = gen;
            } else {
                while (*((volatile unsigned*)&g_gen) != gen) { __nanosleep(20); }
            }
            __threadfence();   // acquire
        }
        __syncthreads();
    }
}

// ---------------------------------------------------------------------------
// Inputs (metadata order): in_seq[1024,128], res_state[8192],
//                          W_in[8192,128], W_res[8192,8192], b_res[8192]
// Output: res_seq[1024,8192] float32
// ---------------------------------------------------------------------------
extern "C" void kernel_launch(void* const* d_in, const int* in_sizes, int n_in,
                              void* d_out, int out_size) {
    const float* in_seq    = (const float*)d_in[0];
    const float* res_state = (const float*)d_in[1];
    const float* W_in      = (const float*)d_in[2];
    const float* W_res     = (const float*)d_in[3];
    const float* b_res     = (const float*)d_in[4];
    float* out = (float*)d_out;

    const int inproj_smem = (128 * 129 + 64 * 128) * sizeof(float);  // ~96.5 KB
    const int esn_smem    = RES * sizeof(float) + RPB * CPIN * sizeof(__half); // 224 KB
    cudaFuncSetAttribute(inproj_kernel, cudaFuncAttributeMaxDynamicSharedMemorySize, inproj_smem);
    cudaFuncSetAttribute(esn_kernel,    cudaFuncAttributeMaxDynamicSharedMemorySize, esn_smem);

    // 1) W_res fp32 -> fp16
    {
        size_t n4 = (size_t)RES * RES / 4;
        int threads = 256;
        int blocks  = (int)(n4 / threads);
        convert_kernel<<<blocks, threads>>>(W_res);
    }

    // 2) in_proj = in_seq @ W_in^T + b
    {
        dim3 grid(RES / 128, TSTEPS / 64);
        inproj_kernel<<<grid, 128, inproj_smem>>>(in_seq, W_in, b_res);
    }

    // 3) persistent recurrent rollout
    esn_kernel<<<NBLK, THREADS, esn_smem>>>(res_state, out);
}

// round 16
// speedup vs baseline: 1.0644x; 1.0644x over previous
#include <cuda_runtime.h>
#include <cuda_fp16.h>
#include <math.h>
#include <stdint.h>

// Problem constants
#define RES    8192
#define TSTEPS 1024
#define SDIM   128

// Main kernel config
#define NBLK    128     // persistent blocks, 1 per SM
#define RPB     64      // rows of W_res per block
#define THREADS 512     // 16 warps, 4 rows per warp
#define RPW     4       // rows per warp
#define CPIN    1536    // cols pinned in SMEM  (64*1536*2B = 192 KB/SM, 24 MiB chip)
#define CREG    1024    // cols pinned in REGISTERS (64 regs/lane, 16 MiB chip)
#define CSTR    (CPIN + CREG)          // 2560: streamed cols start
#define NSTRIT  ((RES - CSTR) / 128)   // 44 streamed 128-col tiles (88 MiB chip)
#define NGRP    4                      // interleave groups
#define SPG     (NSTRIT / NGRP)        // 11 streamed tiles per group
#define PPG     3                      // pinned tiles per group
#define RPG     4                      // register iters per group

// Scratch (static device globals -- no allocations allowed)
__device__ __half  g_Wh[(size_t)RES * RES];            // 128 MiB fp16 weights
__device__ float   g_inproj[(size_t)TSTEPS * RES];     // 32 MiB
__device__ float   g_rbuf[4][RES];                     // quad-buffered state
__device__ unsigned g_flagW[NBLK * 32];                // per-block step flags (128B apart)

// Acquire/release gmem ops for the flag protocol
__device__ __forceinline__ unsigned ldacq(const unsigned* p) {
    unsigned v;
    asm volatile("ld.acquire.gpu.u32 %0, [%1];" : "=r"(v) : "l"(p) : "memory");
    return v;
}
__device__ __forceinline__ void strel(unsigned* p, unsigned v) {
    asm volatile("st.release.gpu.u32 [%0], %1;" :: "l"(p), "r"(v) : "memory");
}

// ---------------------------------------------------------------------------
// fp32 -> fp16 weight conversion; also resets the step flags each replay
// (runs before esn_kernel in stream order on every graph replay).
// ---------------------------------------------------------------------------
__global__ void convert_kernel(const float* __restrict__ W) {
    if (blockIdx.x == 0 && threadIdx.x < NBLK)
        g_flagW[threadIdx.x * 32] = 0u;
    size_t i = ((size_t)blockIdx.x * blockDim.x + threadIdx.x) * 4;
    float4 v = *(const float4*)(W + i);
    __half2* o = (__half2*)(g_Wh + i);
    o[0] = __floats2half2_rn(v.x, v.y);
    o[1] = __floats2half2_rn(v.z, v.w);
}

// ---------------------------------------------------------------------------
// in_proj[t][j] = b[j] + sum_k in_seq[t][k] * W_in[j][k]
// ---------------------------------------------------------------------------
__global__ void inproj_kernel(const float* __restrict__ in_seq,
                              const float* __restrict__ W_in,
                              const float* __restrict__ b_res) {
    extern __shared__ float sm[];
    float* Ws = sm;                 // [128][129] padded
    float* Us = sm + 128 * 129;     // [64][128]
    const int jb  = blockIdx.x * 128;
    const int tb  = blockIdx.y * 64;
    const int tid = threadIdx.x;

    for (int idx = tid; idx < 128 * 128; idx += 128) {
        int r = idx >> 7, k = idx & 127;
        Ws[r * 129 + k] = W_in[(size_t)(jb + r) * SDIM + k];
    }
    for (int idx = tid; idx < 64 * 128; idx += 128) {
        int t = idx >> 7, k = idx & 127;
        Us[idx] = in_seq[(size_t)(tb + t) * SDIM + k];
    }
    __syncthreads();

    const int j = jb + tid;
    const float bj = b_res[j];
    for (int tg = 0; tg < 64; tg += 4) {
        float a0 = bj, a1 = bj, a2 = bj, a3 = bj;
        #pragma unroll 4
        for (int k = 0; k < 128; k++) {
            float w = Ws[tid * 129 + k];
            a0 = fmaf(w, Us[(tg + 0) * 128 + k], a0);
            a1 = fmaf(w, Us[(tg + 1) * 128 + k], a1);
            a2 = fmaf(w, Us[(tg + 2) * 128 + k], a2);
            a3 = fmaf(w, Us[(tg + 3) * 128 + k], a3);
        }
        g_inproj[(size_t)(tb + tg + 0) * RES + j] = a0;
        g_inproj[(size_t)(tb + tg + 1) * RES + j] = a1;
        g_inproj[(size_t)(tb + tg + 2) * RES + j] = a2;
        g_inproj[(size_t)(tb + tg + 3) * RES + j] = a3;
    }
}

// 4 cols (2 packed half2) of one row against 4 r values.
#define ACC4(Q, RV, A, B)                                                     \
{                                                                             \
    float2 _u;                                                                \
    _u = __half22float2(*(__half2*)&(Q).x);                                   \
    (A) = fmaf(_u.x, (RV).x, (A)); (B) = fmaf(_u.y, (RV).y, (B));             \
    _u = __half22float2(*(__half2*)&(Q).y);                                   \
    (A) = fmaf(_u.x, (RV).z, (A)); (B) = fmaf(_u.y, (RV).w, (B));             \
}

// ---------------------------------------------------------------------------
// Persistent recurrent kernel. Per-block slice = 64 rows x 8192 cols fp16:
//   cols [0,1536)     SMEM-pinned, cols [1536,2560) REGISTER-pinned,
//   cols [2560,8192)  streamed, zigzag order (L2-resident under LRU).
// Synchronization: NO global barrier. Producer block b publishes
// flagW[b]=t+1 (release) after writing its 64 rows of step t into
// g_rbuf[t&3]; consumers acquire-poll all 128 flags >= t before loading
// state for step t. Quad buffering bounds skew (a block cannot pass its
// poll at t+3 before everyone published t+2), so fast blocks pipeline one
// step ahead instead of waiting on a lockstep barrier.
// ---------------------------------------------------------------------------
__global__ void __launch_bounds__(THREADS, 1)
esn_kernel(const float* __restrict__ res_state, float* __restrict__ out) {
    extern __shared__ char smraw[];
    float*  r_s  = (float*)smraw;                       // 32 KB state copy
    __half* wpin = (__half*)(smraw + RES * sizeof(float));  // 192 KB pinned W

    const int tid   = threadIdx.x;
    const int rbase = blockIdx.x * RPB;
    const int w     = tid >> 5;
    const int lane  = tid & 31;
    const int lr0   = RPW * w;                     // this warp's first local row
    const int r0g   = rbase + lr0;                 // global first row (mult of 4)

    // Pin SMEM region: cols [0, CPIN) of this block's 64 rows
    for (int idx = tid; idx < RPB * CPIN / 8; idx += THREADS) {
        int r = idx / (CPIN / 8);
        int c = idx % (CPIN / 8);
        *(uint4*)(wpin + r * CPIN + c * 8) =
            *(const uint4*)(g_Wh + (size_t)(rbase + r) * RES + c * 8);
    }

    // Pin REGISTER region: cols [CPIN, CSTR). Lane owns col pair
    // CPIN + 64k + 2*lane, k=0..15, for its 4 rows. 64 uint regs.
    uint32_t wreg[RPW][16];
    #pragma unroll
    for (int j = 0; j < RPW; j++) {
        const __half* src = g_Wh + (size_t)(rbase + lr0 + j) * RES + CPIN + 2 * lane;
        #pragma unroll
        for (int k = 0; k < 16; k++)
            wreg[j][k] = *(const uint32_t*)(src + 64 * k);
    }

    const __half* gw0 = g_Wh + (size_t)(rbase + lr0) * RES;  // row lr0 base
    const __half* sp0 = wpin + lr0 * CPIN;

    for (int t = 0; t < TSTEPS; t++) {
        // ---- wait for all producers to have published step t-1 ----
        if (t > 0 && tid < NBLK) {
            while (ldacq(&g_flagW[tid * 32]) < (unsigned)t) { }
        }
        __syncthreads();

        // Load current state into SMEM. Cross-SM producer -> must bypass L1.
        const float* rsrc = (t == 0) ? res_state : g_rbuf[(t + 3) & 3];
        for (int i = tid; i < RES / 4; i += THREADS)
            ((float4*)r_s)[i] = __ldcg((const float4*)rsrc + i);
        __syncthreads();

        float A0 = 0.f, B0 = 0.f, A1 = 0.f, B1 = 0.f;
        float A2 = 0.f, B2 = 0.f, A3 = 0.f, B3 = 0.f;

        #define STREAM_TILE(IT)                                               \
        {                                                                     \
            int c = CSTR + (IT) * 128 + 4 * lane;                             \
            const __half* gp = gw0 + c;                                       \
            uint2 q0 = *(const uint2*)(gp);                                   \
            uint2 q1 = *(const uint2*)(gp + RES);                             \
            uint2 q2 = *(const uint2*)(gp + 2 * RES);                         \
            uint2 q3 = *(const uint2*)(gp + 3 * RES);                         \
            float4 rv = *(const float4*)(r_s + c);                            \
            ACC4(q0, rv, A0, B0); ACC4(q1, rv, A1, B1);                       \
            ACC4(q2, rv, A2, B2); ACC4(q3, rv, A3, B3);                       \
        }
        #define PIN_TILE(IT)                                                  \
        {                                                                     \
            int c = (IT) * 128 + 4 * lane;                                    \
            const __half* sq = sp0 + c;                                       \
            uint2 q0 = *(const uint2*)(sq);                                   \
            uint2 q1 = *(const uint2*)(sq + CPIN);                            \
            uint2 q2 = *(const uint2*)(sq + 2 * CPIN);                        \
            uint2 q3 = *(const uint2*)(sq + 3 * CPIN);                        \
            float4 rv = *(const float4*)(r_s + c);                            \
            ACC4(q0, rv, A0, B0); ACC4(q1, rv, A1, B1);                       \
            ACC4(q2, rv, A2, B2); ACC4(q3, rv, A3, B3);                       \
        }
        #define REG_IT(K)                                                     \
        {                                                                     \
            float2 rr = *(const float2*)(r_s + CPIN + 64 * (K) + 2 * lane);   \
            float2 u;                                                         \
            u = __half22float2(*(__half2*)&wreg[0][(K)]);                     \
            A0 = fmaf(u.x, rr.x, A0); B0 = fmaf(u.y, rr.y, B0);               \
            u = __half22float2(*(__half2*)&wreg[1][(K)]);                     \
            A1 = fmaf(u.x, rr.x, A1); B1 = fmaf(u.y, rr.y, B1);               \
            u = __half22float2(*(__half2*)&wreg[2][(K)]);                     \
            A2 = fmaf(u.x, rr.x, A2); B2 = fmaf(u.y, rr.y, B2);               \
            u = __half22float2(*(__half2*)&wreg[3][(K)]);                     \
            A3 = fmaf(u.x, rr.x, A3); B3 = fmaf(u.y, rr.y, B3);               \
        }

        // 4 straight-line groups: 11 streamed + 3 pinned + 4 register each.
        if ((t & 1) == 0) {
            #pragma unroll
            for (int grp = 0; grp < NGRP; grp++) {
                #pragma unroll
                for (int j = 0; j < SPG; j++) STREAM_TILE(grp * SPG + j);
                #pragma unroll
                for (int j = 0; j < PPG; j++) PIN_TILE(grp * PPG + j);
                #pragma unroll
                for (int j = 0; j < RPG; j++) REG_IT(grp * RPG + j);
            }
        } else {
            #pragma unroll
            for (int grp = 0; grp < NGRP; grp++) {
                #pragma unroll
                for (int j = 0; j < SPG; j++)
                    STREAM_TILE(NSTRIT - 1 - (grp * SPG + j));
                #pragma unroll
                for (int j = 0; j < PPG; j++) PIN_TILE(grp * PPG + j);
                #pragma unroll
                for (int j = 0; j < RPG; j++) REG_IT(grp * RPG + j);
            }
        }
        #undef STREAM_TILE
        #undef PIN_TILE
        #undef REG_IT

        float s0 = A0 + B0, s1 = A1 + B1, s2 = A2 + B2, s3 = A3 + B3;
        #pragma unroll
        for (int off = 16; off; off >>= 1) {
            s0 += __shfl_xor_sync(0xffffffffu, s0, off);
            s1 += __shfl_xor_sync(0xffffffffu, s1, off);
            s2 += __shfl_xor_sync(0xffffffffu, s2, off);
            s3 += __shfl_xor_sync(0xffffffffu, s3, off);
        }

        if (lane == 0) {
            float4 ipv = *(const float4*)(g_inproj + (size_t)t * RES + r0g);
            float4 y;
            y.x = tanhf(s0 + ipv.x);
            y.y = tanhf(s1 + ipv.y);
            y.z = tanhf(s2 + ipv.z);
            y.w = tanhf(s3 + ipv.w);
            *(float4*)(g_rbuf[t & 3] + r0g) = y;       // state for next step
            *(float4*)(out + (size_t)t * RES + r0g) = y;
            __threadfence();   // make state writes device-visible
        }

        // ---- publish: this block finished step t ----
        __syncthreads();
        if (tid == 0)
            strel(&g_flagW[blockIdx.x * 32], (unsigned)(t + 1));
    }
}

// ---------------------------------------------------------------------------
// Inputs (metadata order): in_seq[1024,128], res_state[8192],
//                          W_in[8192,128], W_res[8192,8192], b_res[8192]
// Output: res_seq[1024,8192] float32
// ---------------------------------------------------------------------------
extern "C" void kernel_launch(void* const* d_in, const int* in_sizes, int n_in,
                              void* d_out, int out_size) {
    const float* in_seq    = (const float*)d_in[0];
    const float* res_state = (const float*)d_in[1];
    const float* W_in      = (const float*)d_in[2];
    const float* W_res     = (const float*)d_in[3];
    const float* b_res     = (const float*)d_in[4];
    float* out = (float*)d_out;

    const int inproj_smem = (128 * 129 + 64 * 128) * sizeof(float);  // ~96.5 KB
    const int esn_smem    = RES * sizeof(float) + RPB * CPIN * sizeof(__half); // 224 KB
    cudaFuncSetAttribute(inproj_kernel, cudaFuncAttributeMaxDynamicSharedMemorySize, inproj_smem);
    cudaFuncSetAttribute(esn_kernel,    cudaFuncAttributeMaxDynamicSharedMemorySize, esn_smem);

    // 1) W_res fp32 -> fp16 (+ flag reset for replay safety)
    {
        size_t n4 = (size_t)RES * RES / 4;
        int threads = 256;
        int blocks  = (int)(n4 / threads);
        convert_kernel<<<blocks, threads>>>(W_res);
    }

    // 2) in_proj = in_seq @ W_in^T + b
    {
        dim3 grid(RES / 128, TSTEPS / 64);
        inproj_kernel<<<grid, 128, inproj_smem>>>(in_seq, W_in, b_res);
    }

    // 3) persistent recurrent rollout (flag-pipelined, no global barrier)
    esn_kernel<<<NBLK, THREADS, esn_smem>>>(res_state, out);
}

// round 17
// speedup vs baseline: 1.0784x; 1.0131x over previous
#include <cuda_runtime.h>
#include <cuda_fp16.h>
#include <math.h>
#include <stdint.h>

// Problem constants
#define RES    8192
#define TSTEPS 1024
#define SDIM   128

// Main kernel config
#define NBLK    128     // persistent blocks, 1 per SM
#define RPB     64      // rows of W_res per block
#define THREADS 512     // 16 warps, 4 rows per warp
#define RPW     4       // rows per warp
#define CPIN    1536    // cols pinned in SMEM  (64*1536*2B = 192 KB/SM, 24 MiB chip)
#define CREG    1024    // cols pinned in REGISTERS (64 regs/lane, 16 MiB chip)
#define CSTR    (CPIN + CREG)          // 2560: streamed cols start
#define NSTRIT  ((RES - CSTR) / 128)   // 44 streamed 128-col tiles (88 MiB chip)
#define NGRP    4                      // interleave groups
#define SPG     (NSTRIT / NGRP)        // 11 streamed tiles per group
#define PPG     3                      // pinned tiles per group
#define RPG     4                      // register iters per group

// Scratch (static device globals -- no allocations allowed)
__device__ __half  g_Wh[(size_t)RES * RES];            // 128 MiB fp16 weights
__device__ float   g_inproj[(size_t)TSTEPS * RES];     // 32 MiB
__device__ float   g_rbuf[4][RES];                     // quad-buffered state
__device__ unsigned g_flagW[NBLK * 32];                // per-block step flags (128B apart)

// Acquire/release gmem ops for the flag protocol
__device__ __forceinline__ unsigned ldacq(const unsigned* p) {
    unsigned v;
    asm volatile("ld.acquire.gpu.u32 %0, [%1];" : "=r"(v) : "l"(p) : "memory");
    return v;
}
__device__ __forceinline__ void strel(unsigned* p, unsigned v) {
    asm volatile("st.release.gpu.u32 [%0], %1;" :: "l"(p), "r"(v) : "memory");
}

// ---------------------------------------------------------------------------
// fp32 -> fp16 weight conversion; also resets the step flags each replay
// (runs before esn_kernel in stream order on every graph replay).
// ---------------------------------------------------------------------------
__global__ void convert_kernel(const float* __restrict__ W) {
    if (blockIdx.x == 0 && threadIdx.x < NBLK)
        g_flagW[threadIdx.x * 32] = 0u;
    size_t i = ((size_t)blockIdx.x * blockDim.x + threadIdx.x) * 4;
    float4 v = *(const float4*)(W + i);
    __half2* o = (__half2*)(g_Wh + i);
    o[0] = __floats2half2_rn(v.x, v.y);
    o[1] = __floats2half2_rn(v.z, v.w);
}

// ---------------------------------------------------------------------------
// in_proj[t][j] = b[j] + sum_k in_seq[t][k] * W_in[j][k]
// ---------------------------------------------------------------------------
__global__ void inproj_kernel(const float* __restrict__ in_seq,
                              const float* __restrict__ W_in,
                              const float* __restrict__ b_res) {
    extern __shared__ float sm[];
    float* Ws = sm;                 // [128][129] padded
    float* Us = sm + 128 * 129;     // [64][128]
    const int jb  = blockIdx.x * 128;
    const int tb  = blockIdx.y * 64;
    const int tid = threadIdx.x;

    for (int idx = tid; idx < 128 * 128; idx += 128) {
        int r = idx >> 7, k = idx & 127;
        Ws[r * 129 + k] = W_in[(size_t)(jb + r) * SDIM + k];
    }
    for (int idx = tid; idx < 64 * 128; idx += 128) {
        int t = idx >> 7, k = idx & 127;
        Us[idx] = in_seq[(size_t)(tb + t) * SDIM + k];
    }
    __syncthreads();

    const int j = jb + tid;
    const float bj = b_res[j];
    for (int tg = 0; tg < 64; tg += 4) {
        float a0 = bj, a1 = bj, a2 = bj, a3 = bj;
        #pragma unroll 4
        for (int k = 0; k < 128; k++) {
            float w = Ws[tid * 129 + k];
            a0 = fmaf(w, Us[(tg + 0) * 128 + k], a0);
            a1 = fmaf(w, Us[(tg + 1) * 128 + k], a1);
            a2 = fmaf(w, Us[(tg + 2) * 128 + k], a2);
            a3 = fmaf(w, Us[(tg + 3) * 128 + k], a3);
        }
        g_inproj[(size_t)(tb + tg + 0) * RES + j] = a0;
        g_inproj[(size_t)(tb + tg + 1) * RES + j] = a1;
        g_inproj[(size_t)(tb + tg + 2) * RES + j] = a2;
        g_inproj[(size_t)(tb + tg + 3) * RES + j] = a3;
    }
}

// 4 cols (2 packed half2) of one row against 4 r values.
#define ACC4(Q, RV, A, B)                                                     \
{                                                                             \
    float2 _u;                                                                \
    _u = __half22float2(*(__half2*)&(Q).x);                                   \
    (A) = fmaf(_u.x, (RV).x, (A)); (B) = fmaf(_u.y, (RV).y, (B));             \
    _u = __half22float2(*(__half2*)&(Q).y);                                   \
    (A) = fmaf(_u.x, (RV).z, (A)); (B) = fmaf(_u.y, (RV).w, (B));             \
}

// ---------------------------------------------------------------------------
// Persistent recurrent kernel. Per-block slice = 64 rows x 8192 cols fp16:
//   cols [0,1536)     SMEM-pinned, cols [1536,2560) REGISTER-pinned,
//   cols [2560,8192)  streamed, zigzag order (L2-resident under LRU).
// Synchronization: NO global barrier. Producer block b publishes
// flagW[b]=t+1 (release) after its state writes; the release-after-
// syncthreads chain carries visibility (message-passing pattern), so
// the per-warp gpu-scope threadfences are gone. The out-store happens
// AFTER the publish -- off the critical path.
// ---------------------------------------------------------------------------
__global__ void __launch_bounds__(THREADS, 1)
esn_kernel(const float* __restrict__ res_state, float* __restrict__ out) {
    extern __shared__ char smraw[];
    float*  r_s  = (float*)smraw;                       // 32 KB state copy
    __half* wpin = (__half*)(smraw + RES * sizeof(float));  // 192 KB pinned W

    const int tid   = threadIdx.x;
    const int rbase = blockIdx.x * RPB;
    const int w     = tid >> 5;
    const int lane  = tid & 31;
    const int lr0   = RPW * w;                     // this warp's first local row
    const int r0g   = rbase + lr0;                 // global first row (mult of 4)

    // Pin SMEM region: cols [0, CPIN) of this block's 64 rows
    for (int idx = tid; idx < RPB * CPIN / 8; idx += THREADS) {
        int r = idx / (CPIN / 8);
        int c = idx % (CPIN / 8);
        *(uint4*)(wpin + r * CPIN + c * 8) =
            *(const uint4*)(g_Wh + (size_t)(rbase + r) * RES + c * 8);
    }

    // Pin REGISTER region: cols [CPIN, CSTR). Lane owns col pair
    // CPIN + 64k + 2*lane, k=0..15, for its 4 rows. 64 uint regs.
    uint32_t wreg[RPW][16];
    #pragma unroll
    for (int j = 0; j < RPW; j++) {
        const __half* src = g_Wh + (size_t)(rbase + lr0 + j) * RES + CPIN + 2 * lane;
        #pragma unroll
        for (int k = 0; k < 16; k++)
            wreg[j][k] = *(const uint32_t*)(src + 64 * k);
    }

    const __half* gw0 = g_Wh + (size_t)(rbase + lr0) * RES;  // row lr0 base
    const __half* sp0 = wpin + lr0 * CPIN;

    for (int t = 0; t < TSTEPS; t++) {
        // ---- wait for all producers to have published step t-1 ----
        if (t > 0 && tid < NBLK) {
            while (ldacq(&g_flagW[tid * 32]) < (unsigned)t) { }
        }
        __syncthreads();

        // Load current state into SMEM. Cross-SM producer -> must bypass L1.
        const float* rsrc = (t == 0) ? res_state : g_rbuf[(t + 3) & 3];
        for (int i = tid; i < RES / 4; i += THREADS)
            ((float4*)r_s)[i] = __ldcg((const float4*)rsrc + i);
        __syncthreads();

        float A0 = 0.f, B0 = 0.f, A1 = 0.f, B1 = 0.f;
        float A2 = 0.f, B2 = 0.f, A3 = 0.f, B3 = 0.f;

        #define STREAM_TILE(IT)                                               \
        {                                                                     \
            int c = CSTR + (IT) * 128 + 4 * lane;                             \
            const __half* gp = gw0 + c;                                       \
            uint2 q0 = *(const uint2*)(gp);                                   \
            uint2 q1 = *(const uint2*)(gp + RES);                             \
            uint2 q2 = *(const uint2*)(gp + 2 * RES);                         \
            uint2 q3 = *(const uint2*)(gp + 3 * RES);                         \
            float4 rv = *(const float4*)(r_s + c);                            \
            ACC4(q0, rv, A0, B0); ACC4(q1, rv, A1, B1);                       \
            ACC4(q2, rv, A2, B2); ACC4(q3, rv, A3, B3);                       \
        }
        #define PIN_TILE(IT)                                                  \
        {                                                                     \
            int c = (IT) * 128 + 4 * lane;                                    \
            const __half* sq = sp0 + c;                                       \
            uint2 q0 = *(const uint2*)(sq);                                   \
            uint2 q1 = *(const uint2*)(sq + CPIN);                            \
            uint2 q2 = *(const uint2*)(sq + 2 * CPIN);                        \
            uint2 q3 = *(const uint2*)(sq + 3 * CPIN);                        \
            float4 rv = *(const float4*)(r_s + c);                            \
            ACC4(q0, rv, A0, B0); ACC4(q1, rv, A1, B1);                       \
            ACC4(q2, rv, A2, B2); ACC4(q3, rv, A3, B3);                       \
        }
        #define REG_IT(K)                                                     \
        {                                                                     \
            float2 rr = *(const float2*)(r_s + CPIN + 64 * (K) + 2 * lane);   \
            float2 u;                                                         \
            u = __half22float2(*(__half2*)&wreg[0][(K)]);                     \
            A0 = fmaf(u.x, rr.x, A0); B0 = fmaf(u.y, rr.y, B0);               \
            u = __half22float2(*(__half2*)&wreg[1][(K)]);                     \
            A1 = fmaf(u.x, rr.x, A1); B1 = fmaf(u.y, rr.y, B1);               \
            u = __half22float2(*(__half2*)&wreg[2][(K)]);                     \
            A2 = fmaf(u.x, rr.x, A2); B2 = fmaf(u.y, rr.y, B2);               \
            u = __half22float2(*(__half2*)&wreg[3][(K)]);                     \
            A3 = fmaf(u.x, rr.x, A3); B3 = fmaf(u.y, rr.y, B3);               \
        }

        // 4 straight-line groups: 11 streamed + 3 pinned + 4 register each.
        if ((t & 1) == 0) {
            #pragma unroll
            for (int grp = 0; grp < NGRP; grp++) {
                #pragma unroll
                for (int j = 0; j < SPG; j++) STREAM_TILE(grp * SPG + j);
                #pragma unroll
                for (int j = 0; j < PPG; j++) PIN_TILE(grp * PPG + j);
                #pragma unroll
                for (int j = 0; j < RPG; j++) REG_IT(grp * RPG + j);
            }
        } else {
            #pragma unroll
            for (int grp = 0; grp < NGRP; grp++) {
                #pragma unroll
                for (int j = 0; j < SPG; j++)
                    STREAM_TILE(NSTRIT - 1 - (grp * SPG + j));
                #pragma unroll
                for (int j = 0; j < PPG; j++) PIN_TILE(grp * PPG + j);
                #pragma unroll
                for (int j = 0; j < RPG; j++) REG_IT(grp * RPG + j);
            }
        }
        #undef STREAM_TILE
        #undef PIN_TILE
        #undef REG_IT

        float s0 = A0 + B0, s1 = A1 + B1, s2 = A2 + B2, s3 = A3 + B3;
        #pragma unroll
        for (int off = 16; off; off >>= 1) {
            s0 += __shfl_xor_sync(0xffffffffu, s0, off);
            s1 += __shfl_xor_sync(0xffffffffu, s1, off);
            s2 += __shfl_xor_sync(0xffffffffu, s2, off);
            s3 += __shfl_xor_sync(0xffffffffu, s3, off);
        }

        float4 y;
        if (lane == 0) {
            float4 ipv = *(const float4*)(g_inproj + (size_t)t * RES + r0g);
            y.x = tanhf(s0 + ipv.x);
            y.y = tanhf(s1 + ipv.y);
            y.z = tanhf(s2 + ipv.z);
            y.w = tanhf(s3 + ipv.w);
            *(float4*)(g_rbuf[t & 3] + r0g) = y;   // state for next step
        }

        // ---- publish: syncthreads gives intra-block happens-before from all
        // warps' state writes to tid 0; st.release.gpu orders them gpu-wide.
        __syncthreads();
        if (tid == 0)
            strel(&g_flagW[blockIdx.x * 32], (unsigned)(t + 1));

        // out store AFTER publish -- off the critical path
        if (lane == 0)
            *(float4*)(out + (size_t)t * RES + r0g) = y;
    }
}

// ---------------------------------------------------------------------------
// Inputs (metadata order): in_seq[1024,128], res_state[8192],
//                          W_in[8192,128], W_res[8192,8192], b_res[8192]
// Output: res_seq[1024,8192] float32
// ---------------------------------------------------------------------------
extern "C" void kernel_launch(void* const* d_in, const int* in_sizes, int n_in,
                              void* d_out, int out_size) {
    const float* in_seq    = (const float*)d_in[0];
    const float* res_state = (const float*)d_in[1];
    const float* W_in      = (const float*)d_in[2];
    const float* W_res     = (const float*)d_in[3];
    const float* b_res     = (const float*)d_in[4];
    float* out = (float*)d_out;

    const int inproj_smem = (128 * 129 + 64 * 128) * sizeof(float);  // ~96.5 KB
    const int esn_smem    = RES * sizeof(float) + RPB * CPIN * sizeof(__half); // 224 KB
    cudaFuncSetAttribute(inproj_kernel, cudaFuncAttributeMaxDynamicSharedMemorySize, inproj_smem);
    cudaFuncSetAttribute(esn_kernel,    cudaFuncAttributeMaxDynamicSharedMemorySize, esn_smem);

    // 1) W_res fp32 -> fp16 (+ flag reset for replay safety)
    {
        size_t n4 = (size_t)RES * RES / 4;
        int threads = 256;
        int blocks  = (int)(n4 / threads);
        convert_kernel<<<blocks, threads>>>(W_res);
    }

    // 2) in_proj = in_seq @ W_in^T + b
    {
        dim3 grid(RES / 128, TSTEPS / 64);
        inproj_kernel<<<grid, 128, inproj_smem>>>(in_seq, W_in, b_res);
    }

    // 3) persistent recurrent rollout (flag-pipelined, no global barrier)
    esn_kernel<<<NBLK, THREADS, esn_smem>>>(res_state, out);
}